// round 7
// baseline (speedup 1.0000x reference)
#include <cuda_runtime.h>

#define N_NODES 50000
#define N_EDGES 800000
#define IN_DIM 64
#define HID_DIM 128
#define OUT_DIM 40
#define NB_SCAN 49   // ceil(50000/1024)
#define HL_STRIDE 64 // padded row stride for g_hl (256B aligned)
#define TILE 128     // nodes per gemm12 block
#define NPAD 129     // node-dim padding in smem

// ---------------- scratch (device globals; zero-initialized at load) ----------------
__device__ int   g_cnt[N_NODES];
__device__ int   g_rowptr[N_NODES + 1];
__device__ int   g_cursor[N_NODES];
__device__ int   g_col[N_EDGES];
__device__ int   g_bsum[NB_SCAN];
__device__ float g_hl[N_NODES * HL_STRIDE]; // h @ Wl2^T (pre-aggregation), padded rows
__device__ float g_hr[N_NODES * OUT_DIM];   // h @ Wr2^T

// ---------------- packed f32x2 helpers ----------------
__device__ __forceinline__ unsigned long long pack2(float v) {
    unsigned long long r;
    asm("mov.b64 %0, {%1, %1};" : "=l"(r) : "f"(v));
    return r;
}
__device__ __forceinline__ void ffma2(unsigned long long& d,
                                      unsigned long long a,
                                      unsigned long long b) {
    asm("fma.rn.f32x2 %0, %1, %2, %0;" : "+l"(d) : "l"(a), "l"(b));
}
__device__ __forceinline__ float2 unpack2(unsigned long long v) {
    float2 r;
    asm("mov.b64 {%0, %1}, %2;" : "=f"(r.x), "=f"(r.y) : "l"(v));
    return r;
}

// ---------------- CSR build ----------------
// invariant: g_cnt == 0 on entry (zero-init at load; re-zeroed by k_scan_add)
__global__ void k_degree(const int* __restrict__ ei) {
    int i = blockIdx.x * blockDim.x + threadIdx.x;
    if (i < N_EDGES) atomicAdd(&g_cnt[ei[N_EDGES + i]], 1);
}

// phase 1: per-block (1024 elems) exclusive scan; block totals to g_bsum
__global__ void __launch_bounds__(1024) k_scan_part() {
    __shared__ int wsum[32];
    int tid = threadIdx.x, lane = tid & 31, warp = tid >> 5;
    int i = blockIdx.x * 1024 + tid;
    int v = (i < N_NODES) ? g_cnt[i] : 0;
    int xs = v;
    #pragma unroll
    for (int off = 1; off < 32; off <<= 1) {
        int t = __shfl_up_sync(0xffffffffu, xs, off);
        if (lane >= off) xs += t;
    }
    if (lane == 31) wsum[warp] = xs;
    __syncthreads();
    if (warp == 0) {
        int s = wsum[lane];
        #pragma unroll
        for (int off = 1; off < 32; off <<= 1) {
            int t = __shfl_up_sync(0xffffffffu, s, off);
            if (lane >= off) s += t;
        }
        wsum[lane] = s;
    }
    __syncthreads();
    int woff = (warp > 0) ? wsum[warp - 1] : 0;
    if (i < N_NODES) g_rowptr[i] = woff + xs - v;   // local exclusive
    if (tid == 1023) g_bsum[blockIdx.x] = woff + xs;
}

// phase 2: add block offsets (warp-0 shfl-scans the 49 totals); also re-zero g_cnt
__global__ void __launch_bounds__(256) k_scan_add() {
    __shared__ int sp[64];            // exclusive prefix of block sums
    __shared__ int s_tot;
    int tid = threadIdx.x;
    if (tid < 32) {
        int lane = tid;
        int v0 = (lane < NB_SCAN) ? g_bsum[lane] : 0;
        int v1 = (32 + lane < NB_SCAN) ? g_bsum[32 + lane] : 0;
        int p0 = v0;
        #pragma unroll
        for (int off = 1; off < 32; off <<= 1) {
            int t = __shfl_up_sync(0xffffffffu, p0, off);
            if (lane >= off) p0 += t;
        }
        int tot0 = __shfl_sync(0xffffffffu, p0, 31);
        int p1 = v1;
        #pragma unroll
        for (int off = 1; off < 32; off <<= 1) {
            int t = __shfl_up_sync(0xffffffffu, p1, off);
            if (lane >= off) p1 += t;
        }
        sp[lane] = p0 - v0;
        sp[32 + lane] = tot0 + p1 - v1;
        if (lane == 31) s_tot = tot0 + p1;
    }
    __syncthreads();
    int i = blockIdx.x * 256 + tid;
    if (i < N_NODES) {
        int r = g_rowptr[i] + sp[i >> 10];
        g_rowptr[i] = r;
        g_cursor[i] = r;
        g_cnt[i] = 0;                 // restore invariant for next invocation
    }
    if (i == 0) g_rowptr[N_NODES] = s_tot;
}

__global__ void k_fill(const int* __restrict__ ei) {
    int i = blockIdx.x * blockDim.x + threadIdx.x;
    if (i < N_EDGES) {
        int s = ei[i];
        int d = ei[N_EDGES + i];
        g_col[atomicAdd(&g_cursor[d], 1)] = s;
    }
}

// ---------------- fused agg1 + layer-1 + layer-2 GEMM, 128-node tiles ----------------
// smem: s_dat[128][129] | s_w1 16384 (L1 packed wts; later s_out[80][129]) |
//       s_w2 10240 (L2 packed wts) | s_b 128
#define G12_SMEM_FLOATS (128 * NPAD + 16384 + 10240 + 128)
__global__ void __launch_bounds__(512) k_gemm12(
    const float* __restrict__ x,
    const float* __restrict__ Wl1, const float* __restrict__ bl1,
    const float* __restrict__ Wr1,
    const float* __restrict__ Wl2, const float* __restrict__ Wr2)
{
    extern __shared__ float sm[];
    float* s_dat = sm;                       // [k(128)][node(129)]; then [o][node] h
    float* s_w1  = sm + 128 * NPAD;          // 16384; reused as s_out after layer 1
    float* s_w2  = s_w1 + 16384;             // 10240
    float* s_b   = s_w2 + 10240;             // 128
    int tid = threadIdx.x;
    int n0 = blockIdx.x * TILE;
    int rem = min(TILE, N_NODES - n0);

    // layer-1 weights, FFMA2-packed: float idx = (o>>1)*128 + (k>>1)*4 + (k&1)*2 + (o&1)
    for (int idx = tid; idx < 8192; idx += 512) {
        int o = idx >> 6, k = idx & 63;
        int dst = ((o >> 1) << 7) + ((k >> 1) << 2) + ((k & 1) << 1) + (o & 1);
        s_w1[dst] = Wl1[idx];
        s_w1[8192 + dst] = Wr1[idx];
    }
    // layer-2 weights (80 outputs: 40 Wl2 then 40 Wr2), FFMA2-packed:
    // float idx = (o>>1)*256 + (k>>1)*4 + (k&1)*2 + (o&1)
    for (int idx = tid; idx < 5120; idx += 512) {
        int o = idx >> 7, k = idx & 127;
        int dst = ((o >> 1) << 8) + ((k >> 1) << 2) + ((k & 1) << 1) + (o & 1);
        s_w2[dst] = Wl2[idx];
        int o2 = o + 40;
        int dst2 = ((o2 >> 1) << 8) + ((k >> 1) << 2) + ((k & 1) << 1) + (o2 & 1);
        s_w2[dst2] = Wr2[idx];
    }
    if (tid < 128) s_b[tid] = bl1[tid];

    // x rows (W_r input) -> s_dat[64..128)[node]
    for (int idx = tid; idx < TILE * 64; idx += 512) {
        int l2 = idx >> 6, k = idx & 63;
        float v = (l2 < rem) ? x[(n0 + l2) * 64 + k] : 0.f;
        s_dat[(64 + k) * NPAD + l2] = v;
    }

    // neighbor mean of x -> s_dat[0..64)[node]  (warp per node, 16 warps, unroll 4)
    {
        int warp = tid >> 5, lane = tid & 31;
        const float2* xp = (const float2*)x;
        for (int wn = warp; wn < TILE; wn += 16) {
            float2 acc = make_float2(0.f, 0.f);
            int deg = 0;
            if (wn < rem) {
                int node = n0 + wn;
                int s = g_rowptr[node], e = g_rowptr[node + 1];
                deg = e - s;
                for (int base = s; base < e; base += 32) {
                    int j = base + lane;
                    int myc = (j < e) ? g_col[j] : 0;
                    int cnt = min(32, e - base);
                    int jj = 0;
                    for (; jj + 4 <= cnt; jj += 4) {
                        int c0 = __shfl_sync(0xffffffffu, myc, jj);
                        int c1 = __shfl_sync(0xffffffffu, myc, jj + 1);
                        int c2 = __shfl_sync(0xffffffffu, myc, jj + 2);
                        int c3 = __shfl_sync(0xffffffffu, myc, jj + 3);
                        float2 v0 = xp[c0 * 32 + lane];
                        float2 v1 = xp[c1 * 32 + lane];
                        float2 v2 = xp[c2 * 32 + lane];
                        float2 v3 = xp[c3 * 32 + lane];
                        acc.x += (v0.x + v1.x) + (v2.x + v3.x);
                        acc.y += (v0.y + v1.y) + (v2.y + v3.y);
                    }
                    for (; jj < cnt; jj++) {
                        int c = __shfl_sync(0xffffffffu, myc, jj);
                        float2 v = xp[c * 32 + lane];
                        acc.x += v.x; acc.y += v.y;
                    }
                }
            }
            float inv = 1.0f / (float)max(deg, 1);
            s_dat[(2 * lane) * NPAD + wn] = acc.x * inv;
            s_dat[(2 * lane + 1) * NPAD + wn] = acc.y * inv;
        }
    }
    __syncthreads();

    // ---- layer 1: 128 outputs, K=64 dual weights, FFMA2 ----
    int l = tid & 127;              // node
    int pbase = (tid >> 7) * 16;    // 16 output pairs -> outputs [32*wg, 32*wg+32)
    unsigned long long d1[16];
    #pragma unroll
    for (int p = 0; p < 16; p++) d1[p] = 0ull;
    {
        const ulonglong2* wl = (const ulonglong2*)s_w1;           // [P*32 + kk]
        const ulonglong2* wr = (const ulonglong2*)(s_w1 + 8192);
        for (int kk = 0; kk < 32; kk++) {
            float m0 = s_dat[(2 * kk) * NPAD + l];
            float m1 = s_dat[(2 * kk + 1) * NPAD + l];
            float y0 = s_dat[(64 + 2 * kk) * NPAD + l];
            float y1 = s_dat[(64 + 2 * kk + 1) * NPAD + l];
            unsigned long long mm0 = pack2(m0), mm1 = pack2(m1);
            unsigned long long yy0 = pack2(y0), yy1 = pack2(y1);
            #pragma unroll
            for (int p = 0; p < 16; p++) {
                ulonglong2 a = wl[(pbase + p) * 32 + kk];
                ffma2(d1[p], a.x, mm0);
                ffma2(d1[p], a.y, mm1);
                ulonglong2 b = wr[(pbase + p) * 32 + kk];
                ffma2(d1[p], b.x, yy0);
                ffma2(d1[p], b.y, yy1);
            }
        }
    }
    __syncthreads();   // done reading s_dat inputs + layer-1 weights

    // h (+bias, relu) -> s_dat[o][node]  (o-major == k-major for layer 2)
    #pragma unroll
    for (int p = 0; p < 16; p++) {
        int o = 2 * (pbase + p);
        float2 v = unpack2(d1[p]);
        s_dat[o * NPAD + l] = fmaxf(v.x + s_b[o], 0.f);
        s_dat[(o + 1) * NPAD + l] = fmaxf(v.y + s_b[o + 1], 0.f);
    }
    __syncthreads();

    // ---- layer 2: 80 outputs, K=128, FFMA2 (weights already resident in s_w2) ----
    int pbase2 = (tid >> 7) * 10;   // 10 pairs -> outputs [20*wg, 20*wg+20)
    unsigned long long d2[10];
    #pragma unroll
    for (int p = 0; p < 10; p++) d2[p] = 0ull;
    {
        const ulonglong2* w2 = (const ulonglong2*)s_w2;   // [P*64 + kk]
        for (int kk = 0; kk < 64; kk++) {
            float h0 = s_dat[(2 * kk) * NPAD + l];
            float h1 = s_dat[(2 * kk + 1) * NPAD + l];
            unsigned long long hh0 = pack2(h0), hh1 = pack2(h1);
            #pragma unroll
            for (int p = 0; p < 10; p++) {
                ulonglong2 a = w2[(pbase2 + p) * 64 + kk];
                ffma2(d2[p], a.x, hh0);
                ffma2(d2[p], a.y, hh1);
            }
        }
    }
    // stage into s_w1 region (dead): s_out[80][129] = 10320 <= 16384
    float* s_out = s_w1;
    #pragma unroll
    for (int p = 0; p < 10; p++) {
        int o = 2 * (pbase2 + p);
        float2 v = unpack2(d2[p]);
        s_out[o * NPAD + l] = v.x;
        s_out[(o + 1) * NPAD + l] = v.y;
    }
    __syncthreads();
    for (int idx = tid; idx < rem * 40; idx += 512) {
        int n = idx / 40, o = idx % 40;
        g_hl[(n0 + n) * HL_STRIDE + o] = s_out[o * NPAD + n];
        g_hr[(n0 + n) * 40 + o] = s_out[(40 + o) * NPAD + n];
    }
}

// ---------------- fused layer-2 aggregation + epilogue (unroll 4) ----------------
__global__ void k_agglout(const float* __restrict__ bl, float* __restrict__ out) {
    int node = (blockIdx.x * blockDim.x + threadIdx.x) >> 5;
    int lane = threadIdx.x & 31;
    if (node >= N_NODES) return;
    int s = g_rowptr[node], e = g_rowptr[node + 1];
    float acc0 = 0.f, acc1 = 0.f;
    for (int base = s; base < e; base += 32) {
        int j = base + lane;
        int myc = (j < e) ? g_col[j] : 0;
        int cnt = min(32, e - base);
        int jj = 0;
        for (; jj + 4 <= cnt; jj += 4) {
            int c0 = __shfl_sync(0xffffffffu, myc, jj);
            int c1 = __shfl_sync(0xffffffffu, myc, jj + 1);
            int c2 = __shfl_sync(0xffffffffu, myc, jj + 2);
            int c3 = __shfl_sync(0xffffffffu, myc, jj + 3);
            float a0 = g_hl[c0 * HL_STRIDE + lane];
            float a1 = g_hl[c1 * HL_STRIDE + lane];
            float a2 = g_hl[c2 * HL_STRIDE + lane];
            float a3 = g_hl[c3 * HL_STRIDE + lane];
            acc0 += (a0 + a1) + (a2 + a3);
            if (lane < 8) {
                float b0 = g_hl[c0 * HL_STRIDE + 32 + lane];
                float b1 = g_hl[c1 * HL_STRIDE + 32 + lane];
                float b2 = g_hl[c2 * HL_STRIDE + 32 + lane];
                float b3 = g_hl[c3 * HL_STRIDE + 32 + lane];
                acc1 += (b0 + b1) + (b2 + b3);
            }
        }
        for (; jj < cnt; jj++) {
            int c = __shfl_sync(0xffffffffu, myc, jj);
            acc0 += g_hl[c * HL_STRIDE + lane];
            if (lane < 8) acc1 += g_hl[c * HL_STRIDE + 32 + lane];
        }
    }
    float inv = 1.0f / (float)max(e - s, 1);
    float v0 = fmaxf(acc0 * inv + g_hr[node * 40 + lane] + bl[lane], 0.f);
    float v1 = 0.f;
    if (lane < 8)
        v1 = fmaxf(acc1 * inv + g_hr[node * 40 + 32 + lane] + bl[32 + lane], 0.f);
    float m = fmaxf(v0, (lane < 8) ? v1 : -1e30f);
    #pragma unroll
    for (int off = 16; off > 0; off >>= 1)
        m = fmaxf(m, __shfl_xor_sync(0xffffffffu, m, off));
    float ssum = expf(v0 - m) + ((lane < 8) ? expf(v1 - m) : 0.f);
    #pragma unroll
    for (int off = 16; off > 0; off >>= 1)
        ssum += __shfl_xor_sync(0xffffffffu, ssum, off);
    float lse = m + logf(ssum);
    out[lane * N_NODES + node] = v0 - lse;
    if (lane < 8) out[(32 + lane) * N_NODES + node] = v1 - lse;
}

// ---------------- launcher ----------------
extern "C" void kernel_launch(void* const* d_in, const int* in_sizes, int n_in,
                              void* d_out, int out_size) {
    const float* x   = (const float*)d_in[0];
    const int*   ei  = (const int*)d_in[1];     // int32 (JAX downcasts int64)
    const float* Wl1 = (const float*)d_in[2];
    const float* bl1 = (const float*)d_in[3];
    const float* Wr1 = (const float*)d_in[4];
    const float* Wl2 = (const float*)d_in[5];
    const float* bl2 = (const float*)d_in[6];
    const float* Wr2 = (const float*)d_in[7];
    float* out = (float*)d_out;

    cudaFuncSetAttribute(k_gemm12, cudaFuncAttributeMaxDynamicSharedMemorySize,
                         G12_SMEM_FLOATS * (int)sizeof(float));

    k_degree<<<(N_EDGES + 255) / 256, 256>>>(ei);
    k_scan_part<<<NB_SCAN, 1024>>>();
    k_scan_add<<<(N_NODES + 255) / 256, 256>>>();
    k_fill<<<(N_EDGES + 255) / 256, 256>>>(ei);
    k_gemm12<<<(N_NODES + TILE - 1) / TILE, 512, G12_SMEM_FLOATS * sizeof(float)>>>(
        x, Wl1, bl1, Wr1, Wl2, Wr2);
    k_agglout<<<(N_NODES + 7) / 8, 256>>>(bl2, out);
}

// round 9
// speedup vs baseline: 1.0431x; 1.0431x over previous
#include <cuda_runtime.h>

#define N_NODES 50000
#define N_EDGES 800000
#define IN_DIM 64
#define HID_DIM 128
#define OUT_DIM 40
#define NB_SCAN 49   // ceil(50000/1024)
#define HL_STRIDE 64 // padded row stride for g_hl (256B aligned)

// ---------------- scratch (device globals; zero-initialized at load) ----------------
__device__ int          g_cnt[N_NODES];
__device__ int          g_rowptr[N_NODES + 1];
__device__ int          g_cursor[N_NODES];
__device__ int          g_col[N_EDGES];
__device__ unsigned int g_scanstate[NB_SCAN];  // lookback: (status<<30)|value; 1=partial 2=inclusive
__device__ float        g_hl[N_NODES * HL_STRIDE]; // h @ Wl2^T (pre-agg), padded rows
__device__ float        g_hr[N_NODES * OUT_DIM];   // h @ Wr2^T

// ---------------- packed f32x2 helpers ----------------
__device__ __forceinline__ unsigned long long pack2(float v) {
    unsigned long long r;
    asm("mov.b64 %0, {%1, %1};" : "=l"(r) : "f"(v));
    return r;
}
__device__ __forceinline__ void ffma2(unsigned long long& d,
                                      unsigned long long a,
                                      unsigned long long b) {
    asm("fma.rn.f32x2 %0, %1, %2, %0;" : "+l"(d) : "l"(a), "l"(b));
}
__device__ __forceinline__ float2 unpack2(unsigned long long v) {
    float2 r;
    asm("mov.b64 {%0, %1}, %2;" : "=f"(r.x), "=f"(r.y) : "l"(v));
    return r;
}

// ---------------- CSR build (3 launches) ----------------
// invariant: g_cnt == 0 on entry (zero-init at load; re-zeroed by k_scan each run)
__global__ void k_degree(const int* __restrict__ ei) {
    if (blockIdx.x == 0 && threadIdx.x < NB_SCAN) g_scanstate[threadIdx.x] = 0u;
    int i = blockIdx.x * blockDim.x + threadIdx.x;
    if (i < N_EDGES) atomicAdd(&g_cnt[ei[N_EDGES + i]], 1);
}

// single-pass exclusive scan with decoupled lookback (49 blocks, all co-resident).
// all status/value packing is UNSIGNED (status in bits 31:30; logical shifts).
__global__ void __launch_bounds__(1024) k_scan() {
    __shared__ int wsum[32];
    __shared__ int s_excl;
    int tid = threadIdx.x, lane = tid & 31, warp = tid >> 5;
    int bid = blockIdx.x;
    int i = bid * 1024 + tid;
    int v = (i < N_NODES) ? g_cnt[i] : 0;
    int xs = v;
    #pragma unroll
    for (int off = 1; off < 32; off <<= 1) {
        int t = __shfl_up_sync(0xffffffffu, xs, off);
        if (lane >= off) xs += t;
    }
    if (lane == 31) wsum[warp] = xs;
    __syncthreads();
    if (warp == 0) {
        int s = wsum[lane];
        #pragma unroll
        for (int off = 1; off < 32; off <<= 1) {
            int t = __shfl_up_sync(0xffffffffu, s, off);
            if (lane >= off) s += t;
        }
        wsum[lane] = s;
    }
    __syncthreads();
    int woff = (warp > 0) ? wsum[warp - 1] : 0;
    int local_excl = woff + xs - v;

    if (tid == 0) {
        unsigned int myTotal = (unsigned int)wsum[31];      // <= 800000 < 2^30
        if (bid == 0) {
            atomicExch(&g_scanstate[0], (2u << 30) | myTotal);
            s_excl = 0;
        } else {
            atomicExch(&g_scanstate[bid], (1u << 30) | myTotal);
            unsigned int sum = 0u;
            int j = bid - 1;
            while (true) {
                unsigned int w = atomicAdd(&g_scanstate[j], 0u);
                unsigned int st = w >> 30;                   // logical shift
                if (st == 0u) continue;                      // not published yet
                sum += (w & 0x3FFFFFFFu);
                if (st == 2u) break;                         // inclusive prefix reached
                j--;
            }
            atomicExch(&g_scanstate[bid], (2u << 30) | (sum + myTotal));
            s_excl = (int)sum;
        }
        if (bid == NB_SCAN - 1) g_rowptr[N_NODES] = s_excl + (int)myTotal;
    }
    __syncthreads();
    if (i < N_NODES) {
        int r = local_excl + s_excl;
        g_rowptr[i] = r;
        g_cursor[i] = r;
        g_cnt[i] = 0;    // restore invariant for the next invocation
    }
}

__global__ void k_fill(const int* __restrict__ ei) {
    int i = blockIdx.x * blockDim.x + threadIdx.x;
    if (i < N_EDGES) {
        int s = ei[i];
        int d = ei[N_EDGES + i];
        g_col[atomicAdd(&g_cursor[d], 1)] = s;
    }
}

// ---------------- fused agg1 + layer-1 + layer-2 GEMM (64-node tiles, 256 thr) ----------------
// smem: s_dat[128][65] | s_w 16384 (packed weights / s_out) | s_b 128
#define G12_SMEM_FLOATS (128 * 65 + 16384 + 128)
__global__ void __launch_bounds__(256) k_gemm12(
    const float* __restrict__ x,
    const float* __restrict__ Wl1, const float* __restrict__ bl1,
    const float* __restrict__ Wr1,
    const float* __restrict__ Wl2, const float* __restrict__ Wr2)
{
    extern __shared__ float sm[];
    float* s_dat = sm;                   // 128*65: [k][node] inputs, then [o][node] h
    float* s_w   = sm + 128 * 65;        // 16384
    float* s_b   = s_w + 16384;          // 128
    int tid = threadIdx.x;
    int n0 = blockIdx.x * 64;
    int rem = min(64, N_NODES - n0);

    // layer-1 weights, FFMA2-packed: float idx = (o>>1)*128 + (k>>1)*4 + (k&1)*2 + (o&1)
    for (int idx = tid; idx < 8192; idx += 256) {
        int o = idx >> 6, k = idx & 63;
        int dst = ((o >> 1) << 7) + ((k >> 1) << 2) + ((k & 1) << 1) + (o & 1);
        s_w[dst] = Wl1[idx];
        s_w[8192 + dst] = Wr1[idx];
    }
    if (tid < 128) s_b[tid] = bl1[tid];

    // x rows (W_r input) -> s_dat[64..128)[node]
    for (int idx = tid; idx < 64 * 64; idx += 256) {
        int l2 = idx >> 6, k = idx & 63;
        float v = (l2 < rem) ? x[(n0 + l2) * 64 + k] : 0.f;
        s_dat[(64 + k) * 65 + l2] = v;
    }

    // neighbor mean of x -> s_dat[0..64)[node]   (warp per node, 8 nodes/warp, unroll 4)
    {
        int warp = tid >> 5, lane = tid & 31;
        const float2* xp = (const float2*)x;
        for (int wn = warp; wn < 64; wn += 8) {
            float2 acc = make_float2(0.f, 0.f);
            int deg = 0;
            if (wn < rem) {
                int node = n0 + wn;
                int s = g_rowptr[node], e = g_rowptr[node + 1];
                deg = e - s;
                for (int base = s; base < e; base += 32) {
                    int j = base + lane;
                    int myc = (j < e) ? g_col[j] : 0;
                    int cnt = min(32, e - base);
                    int jj = 0;
                    for (; jj + 4 <= cnt; jj += 4) {
                        int c0 = __shfl_sync(0xffffffffu, myc, jj);
                        int c1 = __shfl_sync(0xffffffffu, myc, jj + 1);
                        int c2 = __shfl_sync(0xffffffffu, myc, jj + 2);
                        int c3 = __shfl_sync(0xffffffffu, myc, jj + 3);
                        float2 v0 = xp[c0 * 32 + lane];
                        float2 v1 = xp[c1 * 32 + lane];
                        float2 v2 = xp[c2 * 32 + lane];
                        float2 v3 = xp[c3 * 32 + lane];
                        acc.x += (v0.x + v1.x) + (v2.x + v3.x);
                        acc.y += (v0.y + v1.y) + (v2.y + v3.y);
                    }
                    for (; jj < cnt; jj++) {
                        int c = __shfl_sync(0xffffffffu, myc, jj);
                        float2 v = xp[c * 32 + lane];
                        acc.x += v.x; acc.y += v.y;
                    }
                }
            }
            float inv = 1.0f / (float)max(deg, 1);
            s_dat[(2 * lane) * 65 + wn] = acc.x * inv;
            s_dat[(2 * lane + 1) * 65 + wn] = acc.y * inv;
        }
    }
    __syncthreads();

    // ---- layer 1: 128 outputs, K=64 dual weights, FFMA2 ----
    int l = tid & 63;
    int pbase = (tid >> 6) * 16;   // 16 output pairs -> outputs [32*wg, 32*wg+32)
    unsigned long long d1[16];
    #pragma unroll
    for (int p = 0; p < 16; p++) d1[p] = 0ull;
    {
        const ulonglong2* wl = (const ulonglong2*)s_w;            // [P*32 + kk]
        const ulonglong2* wr = (const ulonglong2*)(s_w + 8192);
        for (int kk = 0; kk < 32; kk++) {
            float m0 = s_dat[(2 * kk) * 65 + l];
            float m1 = s_dat[(2 * kk + 1) * 65 + l];
            float y0 = s_dat[(64 + 2 * kk) * 65 + l];
            float y1 = s_dat[(64 + 2 * kk + 1) * 65 + l];
            unsigned long long mm0 = pack2(m0), mm1 = pack2(m1);
            unsigned long long yy0 = pack2(y0), yy1 = pack2(y1);
            #pragma unroll
            for (int p = 0; p < 16; p++) {
                ulonglong2 a = wl[(pbase + p) * 32 + kk];
                ffma2(d1[p], a.x, mm0);
                ffma2(d1[p], a.y, mm1);
                ulonglong2 b = wr[(pbase + p) * 32 + kk];
                ffma2(d1[p], b.x, yy0);
                ffma2(d1[p], b.y, yy1);
            }
        }
    }
    __syncthreads();   // done reading s_dat inputs + layer-1 weights

    // h (+bias, relu) -> s_dat[o][node]  (o-major == k-major for layer 2)
    #pragma unroll
    for (int p = 0; p < 16; p++) {
        int o = 2 * (pbase + p);
        float2 v = unpack2(d1[p]);
        s_dat[o * 65 + l] = fmaxf(v.x + s_b[o], 0.f);
        s_dat[(o + 1) * 65 + l] = fmaxf(v.y + s_b[o + 1], 0.f);
    }
    // layer-2 weights (80 outputs: 40 Wl2 then 40 Wr2), FFMA2-packed
    for (int idx = tid; idx < 5120; idx += 256) {
        int o = idx >> 7, k = idx & 127;
        int dst = ((o >> 1) << 8) + ((k >> 1) << 2) + ((k & 1) << 1) + (o & 1);
        s_w[dst] = Wl2[idx];
        int o2 = o + 40;
        int dst2 = ((o2 >> 1) << 8) + ((k >> 1) << 2) + ((k & 1) << 1) + (o2 & 1);
        s_w[dst2] = Wr2[idx];
    }
    __syncthreads();

    // ---- layer 2: 80 outputs, K=128, FFMA2 ----
    int pbase2 = (tid >> 6) * 10;   // 10 pairs -> outputs [20*wg, 20*wg+20)
    unsigned long long d2[10];
    #pragma unroll
    for (int p = 0; p < 10; p++) d2[p] = 0ull;
    {
        const ulonglong2* w2 = (const ulonglong2*)s_w;    // [P*64 + kk]
        for (int kk = 0; kk < 64; kk++) {
            float h0 = s_dat[(2 * kk) * 65 + l];
            float h1 = s_dat[(2 * kk + 1) * 65 + l];
            unsigned long long hh0 = pack2(h0), hh1 = pack2(h1);
            #pragma unroll
            for (int p = 0; p < 10; p++) {
                ulonglong2 a = w2[(pbase2 + p) * 64 + kk];
                ffma2(d2[p], a.x, hh0);
                ffma2(d2[p], a.y, hh1);
            }
        }
    }
    // stage at s_w+10240 (80*65=5200 <= 6144 free) for coalesced writes
    float* s_out = s_w + 10240;
    #pragma unroll
    for (int p = 0; p < 10; p++) {
        int o = 2 * (pbase2 + p);
        float2 v = unpack2(d2[p]);
        s_out[o * 65 + l] = v.x;
        s_out[(o + 1) * 65 + l] = v.y;
    }
    __syncthreads();
    for (int idx = tid; idx < rem * 40; idx += 256) {
        int n = idx / 40, o = idx % 40;
        g_hl[(n0 + n) * HL_STRIDE + o] = s_out[o * 65 + n];
        g_hr[(n0 + n) * 40 + o] = s_out[(40 + o) * 65 + n];
    }
}

// ---------------- fused layer-2 aggregation + epilogue (unroll 4) ----------------
__global__ void k_agglout(const float* __restrict__ bl, float* __restrict__ out) {
    int node = (blockIdx.x * blockDim.x + threadIdx.x) >> 5;
    int lane = threadIdx.x & 31;
    if (node >= N_NODES) return;
    int s = g_rowptr[node], e = g_rowptr[node + 1];
    float acc0 = 0.f, acc1 = 0.f;
    for (int base = s; base < e; base += 32) {
        int j = base + lane;
        int myc = (j < e) ? g_col[j] : 0;
        int cnt = min(32, e - base);
        int jj = 0;
        for (; jj + 4 <= cnt; jj += 4) {
            int c0 = __shfl_sync(0xffffffffu, myc, jj);
            int c1 = __shfl_sync(0xffffffffu, myc, jj + 1);
            int c2 = __shfl_sync(0xffffffffu, myc, jj + 2);
            int c3 = __shfl_sync(0xffffffffu, myc, jj + 3);
            float a0 = g_hl[c0 * HL_STRIDE + lane];
            float a1 = g_hl[c1 * HL_STRIDE + lane];
            float a2 = g_hl[c2 * HL_STRIDE + lane];
            float a3 = g_hl[c3 * HL_STRIDE + lane];
            acc0 += (a0 + a1) + (a2 + a3);
            if (lane < 8) {
                float b0 = g_hl[c0 * HL_STRIDE + 32 + lane];
                float b1 = g_hl[c1 * HL_STRIDE + 32 + lane];
                float b2 = g_hl[c2 * HL_STRIDE + 32 + lane];
                float b3 = g_hl[c3 * HL_STRIDE + 32 + lane];
                acc1 += (b0 + b1) + (b2 + b3);
            }
        }
        for (; jj < cnt; jj++) {
            int c = __shfl_sync(0xffffffffu, myc, jj);
            acc0 += g_hl[c * HL_STRIDE + lane];
            if (lane < 8) acc1 += g_hl[c * HL_STRIDE + 32 + lane];
        }
    }
    float inv = 1.0f / (float)max(e - s, 1);
    float v0 = fmaxf(acc0 * inv + g_hr[node * 40 + lane] + bl[lane], 0.f);
    float v1 = 0.f;
    if (lane < 8)
        v1 = fmaxf(acc1 * inv + g_hr[node * 40 + 32 + lane] + bl[32 + lane], 0.f);
    float m = fmaxf(v0, (lane < 8) ? v1 : -1e30f);
    #pragma unroll
    for (int off = 16; off > 0; off >>= 1)
        m = fmaxf(m, __shfl_xor_sync(0xffffffffu, m, off));
    float ssum = expf(v0 - m) + ((lane < 8) ? expf(v1 - m) : 0.f);
    #pragma unroll
    for (int off = 16; off > 0; off >>= 1)
        ssum += __shfl_xor_sync(0xffffffffu, ssum, off);
    float lse = m + logf(ssum);
    out[lane * N_NODES + node] = v0 - lse;
    if (lane < 8) out[(32 + lane) * N_NODES + node] = v1 - lse;
}

// ---------------- launcher ----------------
extern "C" void kernel_launch(void* const* d_in, const int* in_sizes, int n_in,
                              void* d_out, int out_size) {
    const float* x   = (const float*)d_in[0];
    const int*   ei  = (const int*)d_in[1];     // int32 (JAX downcasts int64)
    const float* Wl1 = (const float*)d_in[2];
    const float* bl1 = (const float*)d_in[3];
    const float* Wr1 = (const float*)d_in[4];
    const float* Wl2 = (const float*)d_in[5];
    const float* bl2 = (const float*)d_in[6];
    const float* Wr2 = (const float*)d_in[7];
    float* out = (float*)d_out;

    cudaFuncSetAttribute(k_gemm12, cudaFuncAttributeMaxDynamicSharedMemorySize,
                         G12_SMEM_FLOATS * (int)sizeof(float));

    k_degree<<<(N_EDGES + 255) / 256, 256>>>(ei);         // launch 0
    k_scan<<<NB_SCAN, 1024>>>();                          // launch 1
    k_fill<<<(N_EDGES + 255) / 256, 256>>>(ei);           // launch 2
    k_gemm12<<<(N_NODES + 63) / 64, 256, G12_SMEM_FLOATS * sizeof(float)>>>(
        x, Wl1, bl1, Wr1, Wl2, Wr2);                      // launch 3 (profiled)
    k_agglout<<<(N_NODES + 7) / 8, 256>>>(bl2, out);      // launch 4
}

// round 10
// speedup vs baseline: 1.1242x; 1.0777x over previous
#include <cuda_runtime.h>

#define N_NODES 50000
#define N_EDGES 800000
#define IN_DIM 64
#define HID_DIM 128
#define OUT_DIM 40
#define NB_SCAN 49   // ceil(50000/1024)
#define HL_STRIDE 64 // padded row stride for g_hl (256B aligned)

// ---------------- scratch (device globals; zero-initialized at load) ----------------
__device__ int          g_cnt[N_NODES];
__device__ int          g_rowptr[N_NODES + 1];
__device__ int          g_cursor[N_NODES];
__device__ int          g_col[N_EDGES];
__device__ unsigned int g_scanstate[NB_SCAN];  // lookback: (status<<30)|value; 1=partial 2=inclusive
__device__ float        g_hl[N_NODES * HL_STRIDE]; // h @ Wl2^T (pre-agg), padded rows
__device__ float        g_hr[N_NODES * OUT_DIM];   // h @ Wr2^T

// ---------------- packed f32x2 helpers ----------------
__device__ __forceinline__ unsigned long long pack2(float v) {
    unsigned long long r;
    asm("mov.b64 %0, {%1, %1};" : "=l"(r) : "f"(v));
    return r;
}
__device__ __forceinline__ void ffma2(unsigned long long& d,
                                      unsigned long long a,
                                      unsigned long long b) {
    asm("fma.rn.f32x2 %0, %1, %2, %0;" : "+l"(d) : "l"(a), "l"(b));
}
__device__ __forceinline__ float2 unpack2(unsigned long long v) {
    float2 r;
    asm("mov.b64 {%0, %1}, %2;" : "=f"(r.x), "=f"(r.y) : "l"(v));
    return r;
}

// ---------------- CSR build (3 launches) ----------------
// invariant: g_cnt == 0 on entry (zero-init at load; re-zeroed by k_scan each run)
__global__ void k_degree(const int* __restrict__ ei) {
    if (blockIdx.x == 0 && threadIdx.x < NB_SCAN) g_scanstate[threadIdx.x] = 0u;
    int i = blockIdx.x * blockDim.x + threadIdx.x;
    if (i < N_EDGES) atomicAdd(&g_cnt[ei[N_EDGES + i]], 1);
}

// single-pass exclusive scan with decoupled lookback (49 blocks, all co-resident).
__global__ void __launch_bounds__(1024) k_scan() {
    __shared__ int wsum[32];
    __shared__ int s_excl;
    int tid = threadIdx.x, lane = tid & 31, warp = tid >> 5;
    int bid = blockIdx.x;
    int i = bid * 1024 + tid;
    int v = (i < N_NODES) ? g_cnt[i] : 0;
    int xs = v;
    #pragma unroll
    for (int off = 1; off < 32; off <<= 1) {
        int t = __shfl_up_sync(0xffffffffu, xs, off);
        if (lane >= off) xs += t;
    }
    if (lane == 31) wsum[warp] = xs;
    __syncthreads();
    if (warp == 0) {
        int s = wsum[lane];
        #pragma unroll
        for (int off = 1; off < 32; off <<= 1) {
            int t = __shfl_up_sync(0xffffffffu, s, off);
            if (lane >= off) s += t;
        }
        wsum[lane] = s;
    }
    __syncthreads();
    int woff = (warp > 0) ? wsum[warp - 1] : 0;
    int local_excl = woff + xs - v;

    if (tid == 0) {
        unsigned int myTotal = (unsigned int)wsum[31];
        if (bid == 0) {
            atomicExch(&g_scanstate[0], (2u << 30) | myTotal);
            s_excl = 0;
        } else {
            atomicExch(&g_scanstate[bid], (1u << 30) | myTotal);
            unsigned int sum = 0u;
            int j = bid - 1;
            while (true) {
                unsigned int w = atomicAdd(&g_scanstate[j], 0u);
                unsigned int st = w >> 30;
                if (st == 0u) continue;
                sum += (w & 0x3FFFFFFFu);
                if (st == 2u) break;
                j--;
            }
            atomicExch(&g_scanstate[bid], (2u << 30) | (sum + myTotal));
            s_excl = (int)sum;
        }
        if (bid == NB_SCAN - 1) g_rowptr[N_NODES] = s_excl + (int)myTotal;
    }
    __syncthreads();
    if (i < N_NODES) {
        int r = local_excl + s_excl;
        g_rowptr[i] = r;
        g_cursor[i] = r;
        g_cnt[i] = 0;
    }
}

__global__ void k_fill(const int* __restrict__ ei) {
    int i = blockIdx.x * blockDim.x + threadIdx.x;
    if (i < N_EDGES) {
        int s = ei[i];
        int d = ei[N_EDGES + i];
        g_col[atomicAdd(&g_cursor[d], 1)] = s;
    }
}

// ---------------- fused agg1 + layer-1 + layer-2 GEMM (64-node tiles, 256 thr) ----------------
// k-halved weight staging: s_w holds one k-half of one layer's packed weights at a time.
// smem: s_dat[128][65] (33.3KB) | s_w 8192 floats (32KB) | s_b 128  -> 66.6KB => 3 blocks/SM
#define G12_SMEM_FLOATS (128 * 65 + 8192 + 128)
__global__ void __launch_bounds__(256) k_gemm12(
    const float* __restrict__ x,
    const float* __restrict__ Wl1, const float* __restrict__ bl1,
    const float* __restrict__ Wr1,
    const float* __restrict__ Wl2, const float* __restrict__ Wr2)
{
    extern __shared__ float sm[];
    float* s_dat = sm;                   // 128*65: [k][node] inputs, then [o][node] h
    float* s_w   = sm + 128 * 65;        // 8192 floats (one k-half of one layer)
    float* s_b   = s_w + 8192;           // 128
    int tid = threadIdx.x;
    int n0 = blockIdx.x * 64;
    int rem = min(64, N_NODES - n0);

    if (tid < 128) s_b[tid] = bl1[tid];

    // x rows (W_r input) -> s_dat[64..128)[node]
    for (int idx = tid; idx < 64 * 64; idx += 256) {
        int l2 = idx >> 6, k = idx & 63;
        float v = (l2 < rem) ? x[(n0 + l2) * 64 + k] : 0.f;
        s_dat[(64 + k) * 65 + l2] = v;
    }

    // neighbor mean of x -> s_dat[0..64)[node]   (warp per node, 8 nodes/warp, unroll 4)
    {
        int warp = tid >> 5, lane = tid & 31;
        const float2* xp = (const float2*)x;
        for (int wn = warp; wn < 64; wn += 8) {
            float2 acc = make_float2(0.f, 0.f);
            int deg = 0;
            if (wn < rem) {
                int node = n0 + wn;
                int s = g_rowptr[node], e = g_rowptr[node + 1];
                deg = e - s;
                for (int base = s; base < e; base += 32) {
                    int j = base + lane;
                    int myc = (j < e) ? g_col[j] : 0;
                    int cnt = min(32, e - base);
                    int jj = 0;
                    for (; jj + 4 <= cnt; jj += 4) {
                        int c0 = __shfl_sync(0xffffffffu, myc, jj);
                        int c1 = __shfl_sync(0xffffffffu, myc, jj + 1);
                        int c2 = __shfl_sync(0xffffffffu, myc, jj + 2);
                        int c3 = __shfl_sync(0xffffffffu, myc, jj + 3);
                        float2 v0 = xp[c0 * 32 + lane];
                        float2 v1 = xp[c1 * 32 + lane];
                        float2 v2 = xp[c2 * 32 + lane];
                        float2 v3 = xp[c3 * 32 + lane];
                        acc.x += (v0.x + v1.x) + (v2.x + v3.x);
                        acc.y += (v0.y + v1.y) + (v2.y + v3.y);
                    }
                    for (; jj < cnt; jj++) {
                        int c = __shfl_sync(0xffffffffu, myc, jj);
                        float2 v = xp[c * 32 + lane];
                        acc.x += v.x; acc.y += v.y;
                    }
                }
            }
            float inv = 1.0f / (float)max(deg, 1);
            s_dat[(2 * lane) * 65 + wn] = acc.x * inv;
            s_dat[(2 * lane + 1) * 65 + wn] = acc.y * inv;
        }
    }

    // ---- layer 1: 128 outputs, K=64 dual weights, FFMA2, k-halved staging ----
    int l = tid & 63;
    int pbase = (tid >> 6) * 16;   // 16 output pairs -> outputs [32*wg, 32*wg+32)
    unsigned long long d1[16];
    #pragma unroll
    for (int p = 0; p < 16; p++) d1[p] = 0ull;

    #pragma unroll
    for (int half = 0; half < 2; half++) {
        __syncthreads();   // prev consumers of s_w done (also covers gather completion)
        // pack this k-half: wl -> s_w[0..4096), wr -> s_w[4096..8192)
        // float idx in half: o (0..127), kh (0..31); dst=(o>>1)*64+(kh>>1)*4+(kh&1)*2+(o&1)
        for (int idx = tid; idx < 4096; idx += 256) {
            int o = idx >> 5, kh = idx & 31;
            int src = o * 64 + half * 32 + kh;
            int dst = ((o >> 1) << 6) + ((kh >> 1) << 2) + ((kh & 1) << 1) + (o & 1);
            s_w[dst] = Wl1[src];
            s_w[4096 + dst] = Wr1[src];
        }
        __syncthreads();
        const ulonglong2* wl = (const ulonglong2*)s_w;            // [P*16 + kk]
        const ulonglong2* wr = (const ulonglong2*)(s_w + 4096);
        for (int kk = 0; kk < 16; kk++) {
            int kg = half * 32 + 2 * kk;
            float m0 = s_dat[kg * 65 + l];
            float m1 = s_dat[(kg + 1) * 65 + l];
            float y0 = s_dat[(64 + kg) * 65 + l];
            float y1 = s_dat[(64 + kg + 1) * 65 + l];
            unsigned long long mm0 = pack2(m0), mm1 = pack2(m1);
            unsigned long long yy0 = pack2(y0), yy1 = pack2(y1);
            #pragma unroll
            for (int p = 0; p < 16; p++) {
                ulonglong2 a = wl[(pbase + p) * 16 + kk];
                ffma2(d1[p], a.x, mm0);
                ffma2(d1[p], a.y, mm1);
                ulonglong2 b = wr[(pbase + p) * 16 + kk];
                ffma2(d1[p], b.x, yy0);
                ffma2(d1[p], b.y, yy1);
            }
        }
    }
    __syncthreads();   // everyone done reading s_dat inputs

    // h (+bias, relu) -> s_dat[o][node]  (o-major == k-major for layer 2)
    #pragma unroll
    for (int p = 0; p < 16; p++) {
        int o = 2 * (pbase + p);
        float2 v = unpack2(d1[p]);
        s_dat[o * 65 + l] = fmaxf(v.x + s_b[o], 0.f);
        s_dat[(o + 1) * 65 + l] = fmaxf(v.y + s_b[o + 1], 0.f);
    }

    // ---- layer 2: 80 outputs (40 Wl2 + 40 Wr2), K=128, FFMA2, k-halved staging ----
    int pbase2 = (tid >> 6) * 10;   // 10 pairs -> outputs [20*wg, 20*wg+20)
    unsigned long long d2[10];
    #pragma unroll
    for (int p = 0; p < 10; p++) d2[p] = 0ull;

    #pragma unroll
    for (int half = 0; half < 2; half++) {
        __syncthreads();
        // pack: combined out oc (0..79: 0-39=Wl2, 40-79=Wr2), kh (0..63)
        // dst=(oc>>1)*128+(kh>>1)*4+(kh&1)*2+(oc&1); 5120 floats per half
        for (int idx = tid; idx < 5120; idx += 256) {
            int oc = idx >> 6, kh = idx & 63;
            float v = (oc < 40) ? Wl2[oc * 128 + half * 64 + kh]
                                : Wr2[(oc - 40) * 128 + half * 64 + kh];
            int dst = ((oc >> 1) << 7) + ((kh >> 1) << 2) + ((kh & 1) << 1) + (oc & 1);
            s_w[dst] = v;
        }
        __syncthreads();
        const ulonglong2* w2 = (const ulonglong2*)s_w;    // [P*32 + kk]
        for (int kk = 0; kk < 32; kk++) {
            int kg = half * 64 + 2 * kk;
            float h0 = s_dat[kg * 65 + l];
            float h1 = s_dat[(kg + 1) * 65 + l];
            unsigned long long hh0 = pack2(h0), hh1 = pack2(h1);
            #pragma unroll
            for (int p = 0; p < 10; p++) {
                ulonglong2 a = w2[(pbase2 + p) * 32 + kk];
                ffma2(d2[p], a.x, hh0);
                ffma2(d2[p], a.y, hh1);
            }
        }
    }
    __syncthreads();   // done reading s_w (weights); reuse as s_out[80][65]
    float* s_out = s_w;
    #pragma unroll
    for (int p = 0; p < 10; p++) {
        int o = 2 * (pbase2 + p);
        float2 v = unpack2(d2[p]);
        s_out[o * 65 + l] = v.x;
        s_out[(o + 1) * 65 + l] = v.y;
    }
    __syncthreads();
    for (int idx = tid; idx < rem * 40; idx += 256) {
        int n = idx / 40, o = idx % 40;
        g_hl[(n0 + n) * HL_STRIDE + o] = s_out[o * 65 + n];
        g_hr[(n0 + n) * 40 + o] = s_out[(40 + o) * 65 + n];
    }
}

// ---------------- fused layer-2 aggregation + epilogue (unroll 4) ----------------
__global__ void k_agglout(const float* __restrict__ bl, float* __restrict__ out) {
    int node = (blockIdx.x * blockDim.x + threadIdx.x) >> 5;
    int lane = threadIdx.x & 31;
    if (node >= N_NODES) return;
    int s = g_rowptr[node], e = g_rowptr[node + 1];
    float acc0 = 0.f, acc1 = 0.f;
    for (int base = s; base < e; base += 32) {
        int j = base + lane;
        int myc = (j < e) ? g_col[j] : 0;
        int cnt = min(32, e - base);
        int jj = 0;
        for (; jj + 4 <= cnt; jj += 4) {
            int c0 = __shfl_sync(0xffffffffu, myc, jj);
            int c1 = __shfl_sync(0xffffffffu, myc, jj + 1);
            int c2 = __shfl_sync(0xffffffffu, myc, jj + 2);
            int c3 = __shfl_sync(0xffffffffu, myc, jj + 3);
            float a0 = g_hl[c0 * HL_STRIDE + lane];
            float a1 = g_hl[c1 * HL_STRIDE + lane];
            float a2 = g_hl[c2 * HL_STRIDE + lane];
            float a3 = g_hl[c3 * HL_STRIDE + lane];
            acc0 += (a0 + a1) + (a2 + a3);
            if (lane < 8) {
                float b0 = g_hl[c0 * HL_STRIDE + 32 + lane];
                float b1 = g_hl[c1 * HL_STRIDE + 32 + lane];
                float b2 = g_hl[c2 * HL_STRIDE + 32 + lane];
                float b3 = g_hl[c3 * HL_STRIDE + 32 + lane];
                acc1 += (b0 + b1) + (b2 + b3);
            }
        }
        for (; jj < cnt; jj++) {
            int c = __shfl_sync(0xffffffffu, myc, jj);
            acc0 += g_hl[c * HL_STRIDE + lane];
            if (lane < 8) acc1 += g_hl[c * HL_STRIDE + 32 + lane];
        }
    }
    float inv = 1.0f / (float)max(e - s, 1);
    float v0 = fmaxf(acc0 * inv + g_hr[node * 40 + lane] + bl[lane], 0.f);
    float v1 = 0.f;
    if (lane < 8)
        v1 = fmaxf(acc1 * inv + g_hr[node * 40 + 32 + lane] + bl[32 + lane], 0.f);
    float m = fmaxf(v0, (lane < 8) ? v1 : -1e30f);
    #pragma unroll
    for (int off = 16; off > 0; off >>= 1)
        m = fmaxf(m, __shfl_xor_sync(0xffffffffu, m, off));
    float ssum = expf(v0 - m) + ((lane < 8) ? expf(v1 - m) : 0.f);
    #pragma unroll
    for (int off = 16; off > 0; off >>= 1)
        ssum += __shfl_xor_sync(0xffffffffu, ssum, off);
    float lse = m + logf(ssum);
    out[lane * N_NODES + node] = v0 - lse;
    if (lane < 8) out[(32 + lane) * N_NODES + node] = v1 - lse;
}

// ---------------- launcher ----------------
extern "C" void kernel_launch(void* const* d_in, const int* in_sizes, int n_in,
                              void* d_out, int out_size) {
    const float* x   = (const float*)d_in[0];
    const int*   ei  = (const int*)d_in[1];     // int32 (JAX downcasts int64)
    const float* Wl1 = (const float*)d_in[2];
    const float* bl1 = (const float*)d_in[3];
    const float* Wr1 = (const float*)d_in[4];
    const float* Wl2 = (const float*)d_in[5];
    const float* bl2 = (const float*)d_in[6];
    const float* Wr2 = (const float*)d_in[7];
    float* out = (float*)d_out;

    cudaFuncSetAttribute(k_gemm12, cudaFuncAttributeMaxDynamicSharedMemorySize,
                         G12_SMEM_FLOATS * (int)sizeof(float));

    k_degree<<<(N_EDGES + 255) / 256, 256>>>(ei);         // launch 0
    k_scan<<<NB_SCAN, 1024>>>();                          // launch 1
    k_fill<<<(N_EDGES + 255) / 256, 256>>>(ei);           // launch 2
    k_gemm12<<<(N_NODES + 63) / 64, 256, G12_SMEM_FLOATS * sizeof(float)>>>(
        x, Wl1, bl1, Wr1, Wl2, Wr2);                      // launch 3 (profiled)
    k_agglout<<<(N_NODES + 7) / 8, 256>>>(bl2, out);      // launch 4
}

// round 11
// speedup vs baseline: 1.3107x; 1.1659x over previous
#include <cuda_runtime.h>

#define N_NODES 50000
#define N_EDGES 800000
#define IN_DIM 64
#define HID_DIM 128
#define OUT_DIM 40
#define NB_SCAN 49   // ceil(50000/1024)
#define HL_STRIDE 64 // padded row stride for g_hl (256B aligned)
#define DPAD 68      // s_dat row stride (16B-aligned float4 across nodes)

// ---------------- scratch (device globals; zero-initialized at load) ----------------
__device__ int          g_cnt[N_NODES];
__device__ int          g_rowptr[N_NODES + 1];
__device__ int          g_cursor[N_NODES];
__device__ int          g_col[N_EDGES];
__device__ unsigned int g_scanstate[NB_SCAN];  // lookback: (status<<30)|value; 1=partial 2=inclusive
__device__ float        g_hl[N_NODES * HL_STRIDE]; // h @ Wl2^T (pre-agg), padded rows
__device__ float        g_hr[N_NODES * OUT_DIM];   // h @ Wr2^T

// ---------------- packed f32x2 helpers ----------------
__device__ __forceinline__ unsigned long long pack2(float v) {
    unsigned long long r;
    asm("mov.b64 %0, {%1, %1};" : "=l"(r) : "f"(v));
    return r;
}
__device__ __forceinline__ void ffma2(unsigned long long& d,
                                      unsigned long long a,
                                      unsigned long long b) {
    asm("fma.rn.f32x2 %0, %1, %2, %0;" : "+l"(d) : "l"(a), "l"(b));
}
__device__ __forceinline__ float2 unpack2(unsigned long long v) {
    float2 r;
    asm("mov.b64 {%0, %1}, %2;" : "=f"(r.x), "=f"(r.y) : "l"(v));
    return r;
}

// ---------------- CSR build (3 launches) ----------------
// invariant: g_cnt == 0 on entry (zero-init at load; re-zeroed by k_scan each run)
__global__ void k_degree(const int* __restrict__ ei) {
    if (blockIdx.x == 0 && threadIdx.x < NB_SCAN) g_scanstate[threadIdx.x] = 0u;
    int i = blockIdx.x * blockDim.x + threadIdx.x;
    if (i < N_EDGES) atomicAdd(&g_cnt[ei[N_EDGES + i]], 1);
}

// single-pass exclusive scan with decoupled lookback (49 blocks, all co-resident).
__global__ void __launch_bounds__(1024) k_scan() {
    __shared__ int wsum[32];
    __shared__ int s_excl;
    int tid = threadIdx.x, lane = tid & 31, warp = tid >> 5;
    int bid = blockIdx.x;
    int i = bid * 1024 + tid;
    int v = (i < N_NODES) ? g_cnt[i] : 0;
    int xs = v;
    #pragma unroll
    for (int off = 1; off < 32; off <<= 1) {
        int t = __shfl_up_sync(0xffffffffu, xs, off);
        if (lane >= off) xs += t;
    }
    if (lane == 31) wsum[warp] = xs;
    __syncthreads();
    if (warp == 0) {
        int s = wsum[lane];
        #pragma unroll
        for (int off = 1; off < 32; off <<= 1) {
            int t = __shfl_up_sync(0xffffffffu, s, off);
            if (lane >= off) s += t;
        }
        wsum[lane] = s;
    }
    __syncthreads();
    int woff = (warp > 0) ? wsum[warp - 1] : 0;
    int local_excl = woff + xs - v;

    if (tid == 0) {
        unsigned int myTotal = (unsigned int)wsum[31];
        if (bid == 0) {
            atomicExch(&g_scanstate[0], (2u << 30) | myTotal);
            s_excl = 0;
        } else {
            atomicExch(&g_scanstate[bid], (1u << 30) | myTotal);
            unsigned int sum = 0u;
            int j = bid - 1;
            while (true) {
                unsigned int w = atomicAdd(&g_scanstate[j], 0u);
                unsigned int st = w >> 30;
                if (st == 0u) continue;
                sum += (w & 0x3FFFFFFFu);
                if (st == 2u) break;
                j--;
            }
            atomicExch(&g_scanstate[bid], (2u << 30) | (sum + myTotal));
            s_excl = (int)sum;
        }
        if (bid == NB_SCAN - 1) g_rowptr[N_NODES] = s_excl + (int)myTotal;
    }
    __syncthreads();
    if (i < N_NODES) {
        int r = local_excl + s_excl;
        g_rowptr[i] = r;
        g_cursor[i] = r;
        g_cnt[i] = 0;
    }
}

__global__ void k_fill(const int* __restrict__ ei) {
    int i = blockIdx.x * blockDim.x + threadIdx.x;
    if (i < N_EDGES) {
        int s = ei[i];
        int d = ei[N_EDGES + i];
        g_col[atomicAdd(&g_cursor[d], 1)] = s;
    }
}

// ---------------- fused agg1 + layer-1 + layer-2 GEMM ----------------
// 64-node tiles, 256 threads, 4 nodes x 8 outputs per thread (register blocking).
// k-halved weight staging. smem: s_dat[128][68] | s_w 8192 | s_b 128 -> ~68KB, 3 blocks/SM
#define G12_SMEM_FLOATS (128 * DPAD + 8192 + 128)
__global__ void __launch_bounds__(256, 3) k_gemm12(
    const float* __restrict__ x,
    const float* __restrict__ Wl1, const float* __restrict__ bl1,
    const float* __restrict__ Wr1,
    const float* __restrict__ Wl2, const float* __restrict__ Wr2)
{
    extern __shared__ float sm[];
    float* s_dat = sm;                   // [k(128)][node(68)] inputs, then [o][node] h
    float* s_w   = sm + 128 * DPAD;      // 8192 floats (one k-half of one layer)
    float* s_b   = s_w + 8192;           // 128
    int tid = threadIdx.x;
    int n0 = blockIdx.x * 64;
    int rem = min(64, N_NODES - n0);

    if (tid < 128) s_b[tid] = bl1[tid];

    // x rows (W_r input) -> s_dat[64..128)[node]
    for (int idx = tid; idx < 64 * 64; idx += 256) {
        int l2 = idx >> 6, k = idx & 63;
        float v = (l2 < rem) ? x[(n0 + l2) * 64 + k] : 0.f;
        s_dat[(64 + k) * DPAD + l2] = v;
    }

    // neighbor mean of x -> s_dat[0..64)[node]   (warp per node, 8 nodes/warp, unroll 4)
    {
        int warp = tid >> 5, lane = tid & 31;
        const float2* xp = (const float2*)x;
        for (int wn = warp; wn < 64; wn += 8) {
            float2 acc = make_float2(0.f, 0.f);
            int deg = 0;
            if (wn < rem) {
                int node = n0 + wn;
                int s = g_rowptr[node], e = g_rowptr[node + 1];
                deg = e - s;
                for (int base = s; base < e; base += 32) {
                    int j = base + lane;
                    int myc = (j < e) ? g_col[j] : 0;
                    int cnt = min(32, e - base);
                    int jj = 0;
                    for (; jj + 4 <= cnt; jj += 4) {
                        int c0 = __shfl_sync(0xffffffffu, myc, jj);
                        int c1 = __shfl_sync(0xffffffffu, myc, jj + 1);
                        int c2 = __shfl_sync(0xffffffffu, myc, jj + 2);
                        int c3 = __shfl_sync(0xffffffffu, myc, jj + 3);
                        float2 v0 = xp[c0 * 32 + lane];
                        float2 v1 = xp[c1 * 32 + lane];
                        float2 v2 = xp[c2 * 32 + lane];
                        float2 v3 = xp[c3 * 32 + lane];
                        acc.x += (v0.x + v1.x) + (v2.x + v3.x);
                        acc.y += (v0.y + v1.y) + (v2.y + v3.y);
                    }
                    for (; jj < cnt; jj++) {
                        int c = __shfl_sync(0xffffffffu, myc, jj);
                        float2 v = xp[c * 32 + lane];
                        acc.x += v.x; acc.y += v.y;
                    }
                }
            }
            float inv = 1.0f / (float)max(deg, 1);
            s_dat[(2 * lane) * DPAD + wn] = acc.x * inv;
            s_dat[(2 * lane + 1) * DPAD + wn] = acc.y * inv;
        }
    }

    // thread tile: nodes [ng4, ng4+4), output pairs [4*pg, 4*pg+4) (outputs 8pg..8pg+7)
    int ng4 = (tid & 15) << 2;
    int pg  = tid >> 4;           // 0..15

    // ---- layer 1: 128 outputs, K=64 dual weights, FFMA2, k-halved staging ----
    unsigned long long d1[16];    // [n*4+p]
    #pragma unroll
    for (int q = 0; q < 16; q++) d1[q] = 0ull;

    #pragma unroll
    for (int half = 0; half < 2; half++) {
        __syncthreads();   // prev consumers of s_w done (also covers gather completion)
        // pack this k-half: wl -> s_w[0..4096), wr -> s_w[4096..8192)
        for (int idx = tid; idx < 4096; idx += 256) {
            int o = idx >> 5, kh = idx & 31;
            int src = o * 64 + half * 32 + kh;
            int dst = ((o >> 1) << 6) + ((kh >> 1) << 2) + ((kh & 1) << 1) + (o & 1);
            s_w[dst] = Wl1[src];
            s_w[4096 + dst] = Wr1[src];
        }
        __syncthreads();
        const ulonglong2* wl = (const ulonglong2*)s_w;            // [P*16 + kk]
        const ulonglong2* wr = (const ulonglong2*)(s_w + 4096);
        for (int kk = 0; kk < 16; kk++) {
            int kg = half * 32 + 2 * kk;
            // phase A: mean input rows kg, kg+1
            float4 f0 = *(const float4*)&s_dat[kg * DPAD + ng4];
            float4 f1 = *(const float4*)&s_dat[(kg + 1) * DPAD + ng4];
            unsigned long long s0[4], s1[4];
            s0[0] = pack2(f0.x); s0[1] = pack2(f0.y); s0[2] = pack2(f0.z); s0[3] = pack2(f0.w);
            s1[0] = pack2(f1.x); s1[1] = pack2(f1.y); s1[2] = pack2(f1.z); s1[3] = pack2(f1.w);
            #pragma unroll
            for (int p = 0; p < 4; p++) {
                ulonglong2 a = wl[(4 * pg + p) * 16 + kk];
                #pragma unroll
                for (int n = 0; n < 4; n++) {
                    ffma2(d1[n * 4 + p], a.x, s0[n]);
                    ffma2(d1[n * 4 + p], a.y, s1[n]);
                }
            }
            // phase B: x input rows 64+kg, 64+kg+1
            f0 = *(const float4*)&s_dat[(64 + kg) * DPAD + ng4];
            f1 = *(const float4*)&s_dat[(65 + kg) * DPAD + ng4];
            s0[0] = pack2(f0.x); s0[1] = pack2(f0.y); s0[2] = pack2(f0.z); s0[3] = pack2(f0.w);
            s1[0] = pack2(f1.x); s1[1] = pack2(f1.y); s1[2] = pack2(f1.z); s1[3] = pack2(f1.w);
            #pragma unroll
            for (int p = 0; p < 4; p++) {
                ulonglong2 b = wr[(4 * pg + p) * 16 + kk];
                #pragma unroll
                for (int n = 0; n < 4; n++) {
                    ffma2(d1[n * 4 + p], b.x, s0[n]);
                    ffma2(d1[n * 4 + p], b.y, s1[n]);
                }
            }
        }
    }
    __syncthreads();   // everyone done reading s_dat inputs

    // h (+bias, relu) -> s_dat[o][node]  (o-major == k-major for layer 2)
    #pragma unroll
    for (int p = 0; p < 4; p++) {
        int o = 8 * pg + 2 * p;
        float b0 = s_b[o], b1 = s_b[o + 1];
        #pragma unroll
        for (int n = 0; n < 4; n++) {
            float2 v = unpack2(d1[n * 4 + p]);
            s_dat[o * DPAD + ng4 + n] = fmaxf(v.x + b0, 0.f);
            s_dat[(o + 1) * DPAD + ng4 + n] = fmaxf(v.y + b1, 0.f);
        }
    }

    // ---- layer 2: 80 outputs (40 pairs: 0-19=Wl2, 20-39=Wr2), K=128 ----
    // thread pairs: pg+16j for j=0,1,2 (j=2 valid only for pg<8)
    unsigned long long d2[12];    // [n*3+j]
    #pragma unroll
    for (int q = 0; q < 12; q++) d2[q] = 0ull;

    #pragma unroll
    for (int half = 0; half < 2; half++) {
        __syncthreads();
        for (int idx = tid; idx < 5120; idx += 256) {
            int oc = idx >> 6, kh = idx & 63;
            float v = (oc < 40) ? Wl2[oc * 128 + half * 64 + kh]
                                : Wr2[(oc - 40) * 128 + half * 64 + kh];
            int dst = ((oc >> 1) << 7) + ((kh >> 1) << 2) + ((kh & 1) << 1) + (oc & 1);
            s_w[dst] = v;
        }
        __syncthreads();
        const ulonglong2* w2 = (const ulonglong2*)s_w;    // [P*32 + kk]
        for (int kk = 0; kk < 32; kk++) {
            int kg = half * 64 + 2 * kk;
            float4 f0 = *(const float4*)&s_dat[kg * DPAD + ng4];
            float4 f1 = *(const float4*)&s_dat[(kg + 1) * DPAD + ng4];
            unsigned long long h0[4], h1[4];
            h0[0] = pack2(f0.x); h0[1] = pack2(f0.y); h0[2] = pack2(f0.z); h0[3] = pack2(f0.w);
            h1[0] = pack2(f1.x); h1[1] = pack2(f1.y); h1[2] = pack2(f1.z); h1[3] = pack2(f1.w);
            #pragma unroll
            for (int j = 0; j < 3; j++) {
                if (j < 2 || pg < 8) {
                    ulonglong2 a = w2[(pg + 16 * j) * 32 + kk];
                    #pragma unroll
                    for (int n = 0; n < 4; n++) {
                        ffma2(d2[n * 3 + j], a.x, h0[n]);
                        ffma2(d2[n * 3 + j], a.y, h1[n]);
                    }
                }
            }
        }
    }
    __syncthreads();   // done reading s_w (weights) + s_dat (h); reuse s_w as s_out[80][68]
    float* s_out = s_w;
    #pragma unroll
    for (int j = 0; j < 3; j++) {
        if (j < 2 || pg < 8) {
            int o = 2 * (pg + 16 * j);
            #pragma unroll
            for (int n = 0; n < 4; n++) {
                float2 v = unpack2(d2[n * 3 + j]);
                s_out[o * DPAD + ng4 + n] = v.x;
                s_out[(o + 1) * DPAD + ng4 + n] = v.y;
            }
        }
    }
    __syncthreads();
    for (int idx = tid; idx < rem * 40; idx += 256) {
        int n = idx / 40, o = idx % 40;
        g_hl[(n0 + n) * HL_STRIDE + o] = s_out[o * DPAD + n];
        g_hr[(n0 + n) * 40 + o] = s_out[(40 + o) * DPAD + n];
    }
}

// ---------------- fused layer-2 aggregation + epilogue (unroll 4) ----------------
__global__ void k_agglout(const float* __restrict__ bl, float* __restrict__ out) {
    int node = (blockIdx.x * blockDim.x + threadIdx.x) >> 5;
    int lane = threadIdx.x & 31;
    if (node >= N_NODES) return;
    int s = g_rowptr[node], e = g_rowptr[node + 1];
    float acc0 = 0.f, acc1 = 0.f;
    for (int base = s; base < e; base += 32) {
        int j = base + lane;
        int myc = (j < e) ? g_col[j] : 0;
        int cnt = min(32, e - base);
        int jj = 0;
        for (; jj + 4 <= cnt; jj += 4) {
            int c0 = __shfl_sync(0xffffffffu, myc, jj);
            int c1 = __shfl_sync(0xffffffffu, myc, jj + 1);
            int c2 = __shfl_sync(0xffffffffu, myc, jj + 2);
            int c3 = __shfl_sync(0xffffffffu, myc, jj + 3);
            float a0 = g_hl[c0 * HL_STRIDE + lane];
            float a1 = g_hl[c1 * HL_STRIDE + lane];
            float a2 = g_hl[c2 * HL_STRIDE + lane];
            float a3 = g_hl[c3 * HL_STRIDE + lane];
            acc0 += (a0 + a1) + (a2 + a3);
            if (lane < 8) {
                float b0 = g_hl[c0 * HL_STRIDE + 32 + lane];
                float b1 = g_hl[c1 * HL_STRIDE + 32 + lane];
                float b2 = g_hl[c2 * HL_STRIDE + 32 + lane];
                float b3 = g_hl[c3 * HL_STRIDE + 32 + lane];
                acc1 += (b0 + b1) + (b2 + b3);
            }
        }
        for (; jj < cnt; jj++) {
            int c = __shfl_sync(0xffffffffu, myc, jj);
            acc0 += g_hl[c * HL_STRIDE + lane];
            if (lane < 8) acc1 += g_hl[c * HL_STRIDE + 32 + lane];
        }
    }
    float inv = 1.0f / (float)max(e - s, 1);
    float v0 = fmaxf(acc0 * inv + g_hr[node * 40 + lane] + bl[lane], 0.f);
    float v1 = 0.f;
    if (lane < 8)
        v1 = fmaxf(acc1 * inv + g_hr[node * 40 + 32 + lane] + bl[32 + lane], 0.f);
    float m = fmaxf(v0, (lane < 8) ? v1 : -1e30f);
    #pragma unroll
    for (int off = 16; off > 0; off >>= 1)
        m = fmaxf(m, __shfl_xor_sync(0xffffffffu, m, off));
    float ssum = expf(v0 - m) + ((lane < 8) ? expf(v1 - m) : 0.f);
    #pragma unroll
    for (int off = 16; off > 0; off >>= 1)
        ssum += __shfl_xor_sync(0xffffffffu, ssum, off);
    float lse = m + logf(ssum);
    out[lane * N_NODES + node] = v0 - lse;
    if (lane < 8) out[(32 + lane) * N_NODES + node] = v1 - lse;
}

// ---------------- launcher ----------------
extern "C" void kernel_launch(void* const* d_in, const int* in_sizes, int n_in,
                              void* d_out, int out_size) {
    const float* x   = (const float*)d_in[0];
    const int*   ei  = (const int*)d_in[1];     // int32 (JAX downcasts int64)
    const float* Wl1 = (const float*)d_in[2];
    const float* bl1 = (const float*)d_in[3];
    const float* Wr1 = (const float*)d_in[4];
    const float* Wl2 = (const float*)d_in[5];
    const float* bl2 = (const float*)d_in[6];
    const float* Wr2 = (const float*)d_in[7];
    float* out = (float*)d_out;

    cudaFuncSetAttribute(k_gemm12, cudaFuncAttributeMaxDynamicSharedMemorySize,
                         G12_SMEM_FLOATS * (int)sizeof(float));

    k_degree<<<(N_EDGES + 255) / 256, 256>>>(ei);         // launch 0
    k_scan<<<NB_SCAN, 1024>>>();                          // launch 1
    k_fill<<<(N_EDGES + 255) / 256, 256>>>(ei);           // launch 2
    k_gemm12<<<(N_NODES + 63) / 64, 256, G12_SMEM_FLOATS * sizeof(float)>>>(
        x, Wl1, bl1, Wr1, Wl2, Wr2);                      // launch 3 (profiled)
    k_agglout<<<(N_NODES + 7) / 8, 256>>>(bl2, out);      // launch 4
}